// round 2
// baseline (speedup 1.0000x reference)
#include <cuda_runtime.h>
#include <cstdint>

#define DEV_INLINE __device__ __forceinline__

// ---------------- constants ----------------
__constant__ float c_LO[8] = {
    -0.010597401784997278f, 0.032883011666982945f,
     0.030841381835986965f, -0.18703481171888114f,
    -0.02798376941698385f,  0.6308807679295904f,
     0.7148465705525415f,   0.23037781330885523f };
__constant__ float c_HI[8] = {
    -0.23037781330885523f,  0.7148465705525415f,
    -0.6308807679295904f,  -0.02798376941698385f,
     0.18703481171888114f,  0.030841381835986965f,
     0.032883011666982945f, -0.010597401784997278f };

// ---------------- scratch (device globals; no allocation allowed) ----------------
__device__ float g_M[84 * 64];      // DWT matrix: coeff c as linear fn of x[t]
__device__ float g_W[64 * 4096];    // effective weights [k][t*64+hw], tf32-rounded

// =====================================================================
// Kernel 1: build the 84x64 DWT matrix by transforming basis vectors.
// Rows: [0,14)=lo3, [14,49)=hi1, [49,70)=hi2, [70,84)=hi3
// =====================================================================
__global__ void dwt_matrix_kernel() {
    __shared__ float slo1[64 * 37];   // level-1 lowpass, stride 37 (conflict-free)
    __shared__ float slo2[64 * 23];   // level-2 lowpass, stride 23
    const int tid = threadIdx.x;      // 256 threads
    const int t   = tid & 63;         // basis index (column of M)
    const int seg = tid >> 6;         // 4-way split of output coefficients

    // ---- Level 1: n=64 -> 35, reflect pad left 6 ----
    {
        const int i0 = seg * 9;
        const int i1 = (i0 + 9 < 35) ? i0 + 9 : 35;
        for (int i = i0; i < i1; ++i) {
            float lo = 0.f, hi = 0.f;
#pragma unroll
            for (int j = 0; j < 8; ++j) {
                int idx = 2 * i + j - 6;
                if (idx < 0)   idx = -idx;
                if (idx >= 64) idx = 2 * 63 - idx;
                float v = (idx == t) ? 1.0f : 0.0f;
                lo = fmaf(v, c_LO[7 - j], lo);
                hi = fmaf(v, c_HI[7 - j], hi);
            }
            slo1[t * 37 + i]        = lo;
            g_M[(14 + i) * 64 + t]  = hi;
        }
    }
    __syncthreads();

    // ---- Level 2: n=35 -> 21 ----
    {
        const int i0 = seg * 6;
        const int i1 = (i0 + 6 < 21) ? i0 + 6 : 21;
        for (int i = i0; i < i1; ++i) {
            float lo = 0.f, hi = 0.f;
#pragma unroll
            for (int j = 0; j < 8; ++j) {
                int idx = 2 * i + j - 6;
                if (idx < 0)   idx = -idx;
                if (idx >= 35) idx = 2 * 34 - idx;
                float v = slo1[t * 37 + idx];
                lo = fmaf(v, c_LO[7 - j], lo);
                hi = fmaf(v, c_HI[7 - j], hi);
            }
            slo2[t * 23 + i]        = lo;
            g_M[(49 + i) * 64 + t]  = hi;
        }
    }
    __syncthreads();

    // ---- Level 3: n=21 -> 14 ----
    {
        const int i0 = seg * 4;
        const int i1 = (i0 + 4 < 14) ? i0 + 4 : 14;
        for (int i = i0; i < i1; ++i) {
            float lo = 0.f, hi = 0.f;
#pragma unroll
            for (int j = 0; j < 8; ++j) {
                int idx = 2 * i + j - 6;
                if (idx < 0)   idx = -idx;
                if (idx >= 21) idx = 2 * 20 - idx;
                float v = slo2[t * 23 + idx];
                lo = fmaf(v, c_LO[7 - j], lo);
                hi = fmaf(v, c_HI[7 - j], hi);
            }
            g_M[i * 64 + t]         = lo;
            g_M[(70 + i) * 64 + t]  = hi;
        }
    }
}

// =====================================================================
// Kernel 2: Weff[k][t*64+hw] = sum_c M[c][t] * conv_w[k][c][hw], tf32-rounded.
// Grid: 64 blocks (k), 256 threads = (hw 64) x (t-group 4, 16 t each).
// =====================================================================
__global__ void weff_kernel(const float* __restrict__ conv_w) {
    __shared__ float Ms[84 * 64];
    const int tid = threadIdx.x;
    const int k   = blockIdx.x;
    const int hw  = tid & 63;
    const int tg  = tid >> 6;            // t in [tg*16, tg*16+16)

    for (int i = tid; i < 84 * 64; i += 256) Ms[i] = g_M[i];
    __syncthreads();

    float acc[16];
#pragma unroll
    for (int i = 0; i < 16; ++i) acc[i] = 0.f;

#pragma unroll 4
    for (int c = 0; c < 84; ++c) {
        const float v = __ldg(&conv_w[(k * 84 + c) * 64 + hw]);
        const float* m = &Ms[c * 64 + tg * 16];
#pragma unroll
        for (int tt = 0; tt < 16; ++tt) acc[tt] = fmaf(v, m[tt], acc[tt]);
    }

#pragma unroll
    for (int tt = 0; tt < 16; ++tt) {
        const int tcol = tg * 16 + tt;
        uint32_t r;
        asm("cvt.rna.tf32.f32 %0, %1;" : "=r"(r) : "f"(acc[tt]));
        g_W[k * 4096 + tcol * 64 + hw] = __uint_as_float(r);
    }
}

// =====================================================================
// Kernel 3: GEMM  out[8192][64] = X[8192][4096] @ Weff^T, + bias, LeakyReLU.
// tf32 mma.sync.m16n8k8. CTA tile M=64, N=64, KC=64, cp.async double buffer.
// 8 warps = 4(m) x 2(n); warp tile m16 x n32.
// =====================================================================
constexpr int KC           = 64;
constexpr int SSTRIDE      = 68;                    // floats; bank-conflict-free pad
constexpr int STAGE_FLOATS = 64 * SSTRIDE;
constexpr int SMEM_BYTES   = 4 * STAGE_FLOATS * 4;  // A0,A1,B0,B1

DEV_INLINE void cp_async16(void* dst, const void* src) {
    uint32_t d = (uint32_t)__cvta_generic_to_shared(dst);
    asm volatile("cp.async.cg.shared.global [%0], [%1], 16;\n" :: "r"(d), "l"(src));
}
DEV_INLINE uint32_t f2tf32(float f) {
    uint32_t r; asm("cvt.rna.tf32.f32 %0, %1;" : "=r"(r) : "f"(f)); return r;
}

__global__ __launch_bounds__(256, 1)
void gemm_kernel(const float* __restrict__ X,
                 const float* __restrict__ bias,
                 float* __restrict__ out) {
    extern __shared__ float smem[];
    float* As = smem;                       // 2 stages of [64][SSTRIDE]
    float* Bs = smem + 2 * STAGE_FLOATS;    // 2 stages of [64][SSTRIDE]

    const int tid    = threadIdx.x;
    const int lane   = tid & 31;
    const int wid    = tid >> 5;
    const int mbase  = (wid >> 1) * 16;
    const int nbase  = (wid & 1) * 32;
    const int grp    = lane >> 2;           // 0..7
    const int qid    = lane & 3;            // 0..3
    const int mblock = blockIdx.x * 64;

    float acc[4][4];
#pragma unroll
    for (int a = 0; a < 4; ++a)
#pragma unroll
        for (int b = 0; b < 4; ++b) acc[a][b] = 0.f;

    auto issue = [&](int stage, int kc) {
        float* as = As + stage * STAGE_FLOATS;
        float* bs = Bs + stage * STAGE_FLOATS;
#pragma unroll
        for (int j = 0; j < 4; ++j) {
            const int slot = tid + j * 256;     // 0..1023 16B slots
            const int row  = slot >> 4;         // 0..63
            const int c4   = (slot & 15) << 2;  // float offset 0..60
            cp_async16(&as[row * SSTRIDE + c4], &X[(mblock + row) * 4096 + kc + c4]);
            cp_async16(&bs[row * SSTRIDE + c4], &g_W[row * 4096 + kc + c4]);
        }
        asm volatile("cp.async.commit_group;\n");
    };

    issue(0, 0);

#pragma unroll 1
    for (int c = 0; c < 64; ++c) {
        const int cur = c & 1;
        if (c + 1 < 64) {
            issue(cur ^ 1, (c + 1) * KC);
            asm volatile("cp.async.wait_group 1;\n");
        } else {
            asm volatile("cp.async.wait_group 0;\n");
        }
        __syncthreads();

        const float* as = As + cur * STAGE_FLOATS;
        const float* bs = Bs + cur * STAGE_FLOATS;
#pragma unroll
        for (int kk = 0; kk < 8; ++kk) {
            const int k0 = kk * 8;
            const uint32_t a0 = f2tf32(as[(mbase + grp)     * SSTRIDE + k0 + qid]);
            const uint32_t a1 = f2tf32(as[(mbase + grp + 8) * SSTRIDE + k0 + qid]);
            const uint32_t a2 = f2tf32(as[(mbase + grp)     * SSTRIDE + k0 + qid + 4]);
            const uint32_t a3 = f2tf32(as[(mbase + grp + 8) * SSTRIDE + k0 + qid + 4]);
#pragma unroll
            for (int ns = 0; ns < 4; ++ns) {
                const int ncol = nbase + ns * 8 + grp;
                const uint32_t b0 = __float_as_uint(bs[ncol * SSTRIDE + k0 + qid]);     // pre-rounded tf32
                const uint32_t b1 = __float_as_uint(bs[ncol * SSTRIDE + k0 + qid + 4]);
                asm volatile(
                    "mma.sync.aligned.m16n8k8.row.col.f32.tf32.tf32.f32 "
                    "{%0,%1,%2,%3}, {%4,%5,%6,%7}, {%8,%9}, {%0,%1,%2,%3};\n"
                    : "+f"(acc[ns][0]), "+f"(acc[ns][1]), "+f"(acc[ns][2]), "+f"(acc[ns][3])
                    : "r"(a0), "r"(a1), "r"(a2), "r"(a3), "r"(b0), "r"(b1));
            }
        }
        __syncthreads();
    }

    // ---- epilogue: bias + LeakyReLU(0.001), direct store ----
#pragma unroll
    for (int ns = 0; ns < 4; ++ns) {
        const int col = nbase + ns * 8 + qid * 2;
        const float bb0 = bias[col];
        const float bb1 = bias[col + 1];
        const int r0 = mblock + mbase + grp;
        const int r1 = r0 + 8;

        float v00 = acc[ns][0] + bb0; v00 = (v00 >= 0.f) ? v00 : 0.001f * v00;
        float v01 = acc[ns][1] + bb1; v01 = (v01 >= 0.f) ? v01 : 0.001f * v01;
        float v10 = acc[ns][2] + bb0; v10 = (v10 >= 0.f) ? v10 : 0.001f * v10;
        float v11 = acc[ns][3] + bb1; v11 = (v11 >= 0.f) ? v11 : 0.001f * v11;

        *reinterpret_cast<float2*>(&out[r0 * 64 + col]) = make_float2(v00, v01);
        *reinterpret_cast<float2*>(&out[r1 * 64 + col]) = make_float2(v10, v11);
    }
}

// =====================================================================
// Launch
// =====================================================================
extern "C" void kernel_launch(void* const* d_in, const int* in_sizes, int n_in,
                              void* d_out, int out_size) {
    const float* x      = (const float*)d_in[0];   // [8192,1,64,8,8]
    const float* conv_w = (const float*)d_in[1];   // [64,84,8,8]
    const float* conv_b = (const float*)d_in[2];   // [64]
    float*       out    = (float*)d_out;           // [8192,64]

    cudaFuncSetAttribute(gemm_kernel,
                         cudaFuncAttributeMaxDynamicSharedMemorySize, SMEM_BYTES);

    dwt_matrix_kernel<<<1, 256>>>();
    weff_kernel<<<64, 256>>>(conv_w);
    gemm_kernel<<<128, 256, SMEM_BYTES>>>(x, conv_b, out);
}

// round 7
// speedup vs baseline: 1.0468x; 1.0468x over previous
#include <cuda_runtime.h>
#include <cstdint>

#define DEV_INLINE __device__ __forceinline__

// =====================================================================
// Compile-time DWT matrix: coeff[c] = sum_t M[c][t] * x[t]   (84 x 64)
// =====================================================================
struct MArr { float v[84 * 64]; };

constexpr int refl(int i, int n) {
    if (i < 0) i = -i;
    if (i >= n) i = 2 * (n - 1) - i;
    return i;
}

constexpr MArr build_M() {
    const float LO[8] = { -0.010597401784997278f, 0.032883011666982945f,
                           0.030841381835986965f, -0.18703481171888114f,
                          -0.02798376941698385f,  0.6308807679295904f,
                           0.7148465705525415f,   0.23037781330885523f };
    const float HI[8] = { -0.23037781330885523f,  0.7148465705525415f,
                          -0.6308807679295904f,  -0.02798376941698385f,
                           0.18703481171888114f,  0.030841381835986965f,
                           0.032883011666982945f, -0.010597401784997278f };
    MArr m{};
    for (int t = 0; t < 64; ++t) {
        float lo1[35] = {}, hi1[35] = {};
        float lo2[21] = {}, hi2[21] = {};
        for (int i = 0; i < 35; ++i) {
            float l = 0.f, h = 0.f;
            for (int j = 0; j < 8; ++j) {
                int idx = refl(2 * i + j - 6, 64);
                float xv = (idx == t) ? 1.0f : 0.0f;
                l += xv * LO[7 - j]; h += xv * HI[7 - j];
            }
            lo1[i] = l; hi1[i] = h;
        }
        for (int i = 0; i < 21; ++i) {
            float l = 0.f, h = 0.f;
            for (int j = 0; j < 8; ++j) {
                int idx = refl(2 * i + j - 6, 35);
                l += lo1[idx] * LO[7 - j]; h += lo1[idx] * HI[7 - j];
            }
            lo2[i] = l; hi2[i] = h;
        }
        for (int i = 0; i < 14; ++i) {
            float l = 0.f, h = 0.f;
            for (int j = 0; j < 8; ++j) {
                int idx = refl(2 * i + j - 6, 21);
                l += lo2[idx] * LO[7 - j]; h += lo2[idx] * HI[7 - j];
            }
            m.v[i * 64 + t]        = l;   // lo3
            m.v[(70 + i) * 64 + t] = h;   // hi3
        }
        for (int i = 0; i < 35; ++i) m.v[(14 + i) * 64 + t] = hi1[i];
        for (int i = 0; i < 21; ++i) m.v[(49 + i) * 64 + t] = hi2[i];
    }
    return m;
}

constexpr MArr M_TBL = build_M();
__device__ const MArr g_Mc = M_TBL;

__device__ float g_W[64 * 4096];   // Weff[k][t*64+hw], tf32-rounded

// =====================================================================
// Kernel A: Weff[k][t*64+hw] = sum_c M[c][t] * conv_w[k][c][hw]
// =====================================================================
__global__ void weff_kernel(const float* __restrict__ conv_w) {
    __shared__ float Ms[84 * 64];
    const int tid = threadIdx.x;
    const int k   = blockIdx.x;
    const int hw  = tid & 63;
    const int tg  = tid >> 6;

    for (int i = tid; i < 84 * 64; i += 256) Ms[i] = g_Mc.v[i];
    __syncthreads();

    float acc[16];
#pragma unroll
    for (int i = 0; i < 16; ++i) acc[i] = 0.f;

#pragma unroll 4
    for (int c = 0; c < 84; ++c) {
        const float v = __ldg(&conv_w[(k * 84 + c) * 64 + hw]);
        const float* m = &Ms[c * 64 + tg * 16];
#pragma unroll
        for (int tt = 0; tt < 16; ++tt) acc[tt] = fmaf(v, m[tt], acc[tt]);
    }
#pragma unroll
    for (int tt = 0; tt < 16; ++tt) {
        const int tcol = tg * 16 + tt;
        uint32_t r;
        asm("cvt.rna.tf32.f32 %0, %1;" : "=r"(r) : "f"(acc[tt]));
        g_W[k * 4096 + tcol * 64 + hw] = __uint_as_float(r);
    }
}

// =====================================================================
// Kernel B: tf32 mma.sync GEMM  out[8192][64] = X[8192][4096] @ W^T
//           + bias + LeakyReLU(0.001)
// CTA: M=64, N=64, KC=64/stage, 4-stage cp.async, ldmatrix fragments.
// 8 warps = 4(m) x 2(n); warp tile m16 x n32.
// =====================================================================
constexpr int ROWB  = 272;                   // bytes per smem row (64 f32 + 16B pad)
constexpr int STG   = 64 * ROWB;             // 17408 B per operand stage
constexpr int A_OFF = 0;
constexpr int B_OFF = 4 * STG;               // 69632
constexpr int BIAS_OFF = 8 * STG;            // 139264
constexpr int SMEM_REQ = BIAS_OFF + 256 + 1024;

DEV_INLINE void cp16(uint32_t daddr, const void* src) {
    asm volatile("cp.async.cg.shared.global [%0], [%1], 16;\n" :: "r"(daddr), "l"(src));
}
DEV_INLINE void ldsm_x4(uint32_t& r0, uint32_t& r1, uint32_t& r2, uint32_t& r3,
                        uint32_t addr) {
    asm volatile("ldmatrix.sync.aligned.m8n8.x4.shared.b16 {%0,%1,%2,%3}, [%4];"
                 : "=r"(r0), "=r"(r1), "=r"(r2), "=r"(r3) : "r"(addr));
}
DEV_INLINE uint32_t f2tf32(uint32_t f) {
    uint32_t r; asm("cvt.rna.tf32.f32 %0, %1;" : "=r"(r) : "r"(f)); return r;
}

__global__ __launch_bounds__(256, 1)
void gemm_kernel(const float* __restrict__ X,
                 const float* __restrict__ bias,
                 float* __restrict__ out) {
    extern __shared__ char dsm[];
    uint32_t raw;
    asm("{ .reg .u64 t; cvta.to.shared.u64 t, %1; cvt.u32.u64 %0, t; }"
        : "=r"(raw) : "l"(dsm));
    const uint32_t ab = (raw + 1023u) & ~1023u;
    char* abp = dsm + (ab - raw);

    const int tid    = threadIdx.x;
    const int lane   = tid & 31;
    const int wid    = tid >> 5;
    const int mbase  = (wid >> 1) * 16;      // warp m origin within CTA tile
    const int nbase  = (wid & 1) * 32;       // warp n origin
    const int mblock = blockIdx.x * 64;

    if (tid < 64) *(float*)(abp + BIAS_OFF + tid * 4) = bias[tid];

    // ---- per-lane ldmatrix base offsets (byte offsets within a stage) ----
    // A x4: lanes[0:8)=a0 rows m..m+7 klo | [8:16)=a1 rows m+8.. klo |
    //       [16:24)=a2 rows m..m+7 khi   | [24:32)=a3 rows m+8.. khi
    const int aRow  = mbase + ((lane >> 3) & 1) * 8 + (lane & 7);
    const uint32_t aOffBase = (uint32_t)(aRow * ROWB + ((lane >> 4) & 1) * 16);
    // B x4 (pair p): lanes[0:8)=b0(nb) klo | [8:16)=b1(nb) khi |
    //                [16:24)=b0(nb+1) klo | [24:32)=b1(nb+1) khi
    const int bRow0 = nbase + ((lane >> 4) & 1) * 8 + (lane & 7);
    const uint32_t bHalf = (uint32_t)(((lane >> 3) & 1) * 16);
    const uint32_t bOff0 = (uint32_t)(bRow0 * ROWB) + bHalf;            // nb pair 0
    const uint32_t bOff1 = (uint32_t)((bRow0 + 16) * ROWB) + bHalf;     // nb pair 1

    float acc[4][4];
#pragma unroll
    for (int a = 0; a < 4; ++a)
#pragma unroll
        for (int b = 0; b < 4; ++b) acc[a][b] = 0.f;

    // ---- producer: one KC=64 chunk into stage st ----
    auto issue_stage = [&](int chunk, int st) {
        const int kbase = chunk * 64;
#pragma unroll
        for (int j = 0; j < 8; ++j) {
            const int id = tid + j * 256;
            if (j < 4) {                                  // A: 1024 x 16B
                const int row = id >> 4, c16 = id & 15;
                cp16(ab + A_OFF + st * STG + row * ROWB + c16 * 16,
                     X + (size_t)(mblock + row) * 4096 + kbase + c16 * 4);
            } else {                                      // B: 1024 x 16B
                const int id2 = id - 1024;
                const int row = id2 >> 4, c16 = id2 & 15;
                cp16(ab + B_OFF + st * STG + row * ROWB + c16 * 16,
                     g_W + (size_t)row * 4096 + kbase + c16 * 4);
            }
        }
    };

    // prologue: stages 0..2
#pragma unroll
    for (int p = 0; p < 3; ++p) {
        issue_stage(p, p);
        asm volatile("cp.async.commit_group;\n" ::: "memory");
    }

#pragma unroll 1
    for (int c = 0; c < 64; ++c) {
        const int st = c & 3;
        asm volatile("cp.async.wait_group 2;\n" ::: "memory");
        __syncthreads();

        // issue next chunk first (overlaps with compute below)
        if (c + 3 < 64) issue_stage(c + 3, (c + 3) & 3);
        asm volatile("cp.async.commit_group;\n" ::: "memory");

        const uint32_t aS = ab + A_OFF + st * STG + aOffBase;
        const uint32_t b0S = ab + B_OFF + st * STG + bOff0;
        const uint32_t b1S = ab + B_OFF + st * STG + bOff1;

        uint32_t af[2][4], bf[2][8];
        ldsm_x4(af[0][0], af[0][1], af[0][2], af[0][3], aS);
        ldsm_x4(bf[0][0], bf[0][1], bf[0][2], bf[0][3], b0S);
        ldsm_x4(bf[0][4], bf[0][5], bf[0][6], bf[0][7], b1S);

#pragma unroll
        for (int kk = 0; kk < 8; ++kk) {
            const int cur = kk & 1, nxt = cur ^ 1;
            if (kk < 7) {
                const uint32_t kadd = (uint32_t)((kk + 1) * 32);
                ldsm_x4(af[nxt][0], af[nxt][1], af[nxt][2], af[nxt][3], aS + kadd);
                ldsm_x4(bf[nxt][0], bf[nxt][1], bf[nxt][2], bf[nxt][3], b0S + kadd);
                ldsm_x4(bf[nxt][4], bf[nxt][5], bf[nxt][6], bf[nxt][7], b1S + kadd);
            }
            const uint32_t a0 = f2tf32(af[cur][0]);
            const uint32_t a1 = f2tf32(af[cur][1]);
            const uint32_t a2 = f2tf32(af[cur][2]);
            const uint32_t a3 = f2tf32(af[cur][3]);
#pragma unroll
            for (int ns = 0; ns < 4; ++ns) {
                asm volatile(
                    "mma.sync.aligned.m16n8k8.row.col.f32.tf32.tf32.f32 "
                    "{%0,%1,%2,%3}, {%4,%5,%6,%7}, {%8,%9}, {%0,%1,%2,%3};\n"
                    : "+f"(acc[ns][0]), "+f"(acc[ns][1]),
                      "+f"(acc[ns][2]), "+f"(acc[ns][3])
                    : "r"(a0), "r"(a1), "r"(a2), "r"(a3),
                      "r"(bf[cur][ns * 2]), "r"(bf[cur][ns * 2 + 1]));
            }
        }
    }

    // ---- epilogue: bias + LeakyReLU, direct store ----
    const float* biasS = (const float*)(abp + BIAS_OFF);
    const int grp = lane >> 2, qid = lane & 3;
#pragma unroll
    for (int ns = 0; ns < 4; ++ns) {
        const int col = nbase + ns * 8 + qid * 2;
        const float bb0 = biasS[col];
        const float bb1 = biasS[col + 1];
        const int r0 = mblock + mbase + grp;
        const int r1 = r0 + 8;

        float v00 = acc[ns][0] + bb0; v00 = (v00 >= 0.f) ? v00 : 0.001f * v00;
        float v01 = acc[ns][1] + bb1; v01 = (v01 >= 0.f) ? v01 : 0.001f * v01;
        float v10 = acc[ns][2] + bb0; v10 = (v10 >= 0.f) ? v10 : 0.001f * v10;
        float v11 = acc[ns][3] + bb1; v11 = (v11 >= 0.f) ? v11 : 0.001f * v11;

        *reinterpret_cast<float2*>(&out[(size_t)r0 * 64 + col]) = make_float2(v00, v01);
        *reinterpret_cast<float2*>(&out[(size_t)r1 * 64 + col]) = make_float2(v10, v11);
    }
}

// =====================================================================
// Launch
// =====================================================================
extern "C" void kernel_launch(void* const* d_in, const int* in_sizes, int n_in,
                              void* d_out, int out_size) {
    const float* x      = (const float*)d_in[0];   // [8192,1,64,8,8]
    const float* conv_w = (const float*)d_in[1];   // [64,84,8,8]
    const float* conv_b = (const float*)d_in[2];   // [64]
    float*       out    = (float*)d_out;           // [8192,64]

    cudaFuncSetAttribute(gemm_kernel,
                         cudaFuncAttributeMaxDynamicSharedMemorySize, SMEM_REQ);

    weff_kernel<<<64, 256>>>(conv_w);
    gemm_kernel<<<128, 256, SMEM_REQ>>>(x, conv_b, out);
}

// round 8
// speedup vs baseline: 1.1448x; 1.0936x over previous
#include <cuda_runtime.h>
#include <cstdint>

#define DEV_INLINE __device__ __forceinline__

// =====================================================================
// Compile-time DWT matrix: coeff[c] = sum_t M[c][t] * x[t]   (84 x 64)
// =====================================================================
struct MArr { float v[84 * 64]; };

constexpr int refl(int i, int n) {
    if (i < 0) i = -i;
    if (i >= n) i = 2 * (n - 1) - i;
    return i;
}

constexpr MArr build_M() {
    const float LO[8] = { -0.010597401784997278f, 0.032883011666982945f,
                           0.030841381835986965f, -0.18703481171888114f,
                          -0.02798376941698385f,  0.6308807679295904f,
                           0.7148465705525415f,   0.23037781330885523f };
    const float HI[8] = { -0.23037781330885523f,  0.7148465705525415f,
                          -0.6308807679295904f,  -0.02798376941698385f,
                           0.18703481171888114f,  0.030841381835986965f,
                           0.032883011666982945f, -0.010597401784997278f };
    MArr m{};
    for (int t = 0; t < 64; ++t) {
        float lo1[35] = {}, hi1[35] = {};
        float lo2[21] = {}, hi2[21] = {};
        for (int i = 0; i < 35; ++i) {
            float l = 0.f, h = 0.f;
            for (int j = 0; j < 8; ++j) {
                int idx = refl(2 * i + j - 6, 64);
                float xv = (idx == t) ? 1.0f : 0.0f;
                l += xv * LO[7 - j]; h += xv * HI[7 - j];
            }
            lo1[i] = l; hi1[i] = h;
        }
        for (int i = 0; i < 21; ++i) {
            float l = 0.f, h = 0.f;
            for (int j = 0; j < 8; ++j) {
                int idx = refl(2 * i + j - 6, 35);
                l += lo1[idx] * LO[7 - j]; h += lo1[idx] * HI[7 - j];
            }
            lo2[i] = l; hi2[i] = h;
        }
        for (int i = 0; i < 14; ++i) {
            float l = 0.f, h = 0.f;
            for (int j = 0; j < 8; ++j) {
                int idx = refl(2 * i + j - 6, 21);
                l += lo2[idx] * LO[7 - j]; h += lo2[idx] * HI[7 - j];
            }
            m.v[i * 64 + t]        = l;   // lo3
            m.v[(70 + i) * 64 + t] = h;   // hi3
        }
        for (int i = 0; i < 35; ++i) m.v[(14 + i) * 64 + t] = hi1[i];
        for (int i = 0; i < 21; ++i) m.v[(49 + i) * 64 + t] = hi2[i];
    }
    return m;
}

constexpr MArr M_TBL = build_M();
__device__ const MArr g_Mc = M_TBL;

__device__ float g_W[64 * 4096];   // Weff[k][t*64+hw], tf32-rounded

// =====================================================================
// Kernel A: Weff[k][t*64+hw] = sum_c M[c][t] * conv_w[k][c][hw]
// grid (64 k, 4 t-quarters), 256 threads. All operands staged via smem
// with batched (high-MLP) global loads.
// =====================================================================
__global__ void weff_kernel(const float* __restrict__ conv_w) {
    __shared__ float cw[84 * 64];    // conv_w slice for this k
    __shared__ float Ms[84 * 16];    // M columns for this t-quarter
    const int k   = blockIdx.x;
    const int q   = blockIdx.y;
    const int tid = threadIdx.x;

    for (int i = tid; i < 84 * 64; i += 256) cw[i] = conv_w[k * 84 * 64 + i];
    for (int i = tid; i < 84 * 16; i += 256) {
        const int c = i >> 4, tt = i & 15;
        Ms[i] = g_Mc.v[c * 64 + q * 16 + tt];
    }
    __syncthreads();

    const int hw = tid & 63;
    const int tg = tid >> 6;         // 4 t's per thread
    float acc[4] = {0.f, 0.f, 0.f, 0.f};

#pragma unroll 6
    for (int c = 0; c < 84; ++c) {
        const float v = cw[c * 64 + hw];
        const float* m = &Ms[c * 16 + tg * 4];
#pragma unroll
        for (int i = 0; i < 4; ++i) acc[i] = fmaf(v, m[i], acc[i]);
    }
#pragma unroll
    for (int i = 0; i < 4; ++i) {
        const int t = q * 16 + tg * 4 + i;
        uint32_t r;
        asm("cvt.rna.tf32.f32 %0, %1;" : "=r"(r) : "f"(acc[i]));
        g_W[k * 4096 + t * 64 + hw] = __uint_as_float(r);
    }
}

// =====================================================================
// Kernel B: tf32 mma.sync GEMM  out[8192][64] = X[8192][4096] @ W^T
//           + bias + LeakyReLU(0.001)
// Grid (128 m-tiles, 2 n-halves): CTA tile M=64, N=32, 256 threads,
// 2 CTAs/SM (16 warps/SM). KC=64/stage, 4-stage cp.async, ldmatrix.
// 8 warps = 4(m) x 2(n); warp tile m16 x n16.
// =====================================================================
constexpr int ROWB  = 272;                   // 64 f32 + 16B pad
constexpr int A_STG = 64 * ROWB;             // 17408
constexpr int B_STG = 32 * ROWB;             // 8704
constexpr int A_OFF = 0;
constexpr int B_OFF = 4 * A_STG;             // 69632
constexpr int SMEM_REQ = B_OFF + 4 * B_STG;  // 104448

DEV_INLINE void cp16(uint32_t daddr, const void* src) {
    asm volatile("cp.async.cg.shared.global [%0], [%1], 16;\n" :: "r"(daddr), "l"(src));
}
DEV_INLINE void ldsm_x4(uint32_t* r, uint32_t addr) {
    asm volatile("ldmatrix.sync.aligned.m8n8.x4.shared.b16 {%0,%1,%2,%3}, [%4];"
                 : "=r"(r[0]), "=r"(r[1]), "=r"(r[2]), "=r"(r[3]) : "r"(addr));
}
DEV_INLINE uint32_t f2tf32(uint32_t f) {
    uint32_t r; asm("cvt.rna.tf32.f32 %0, %1;" : "=r"(r) : "r"(f)); return r;
}

__global__ __launch_bounds__(256, 2)
void gemm_kernel(const float* __restrict__ X,
                 const float* __restrict__ bias,
                 float* __restrict__ out) {
    extern __shared__ char dsm[];
    uint32_t ab;
    asm("{ .reg .u64 t; cvta.to.shared.u64 t, %1; cvt.u32.u64 %0, t; }"
        : "=r"(ab) : "l"(dsm));

    const int tid    = threadIdx.x;
    const int lane   = tid & 31;
    const int wid    = tid >> 5;
    const int mbase  = (wid >> 1) * 16;      // warp m origin in CTA tile
    const int nbase  = (wid & 1) * 16;       // warp n origin in CTA tile
    const int mblock = blockIdx.x * 64;
    const int by     = blockIdx.y;           // n-half: cols [32*by, 32*by+32)
    const float* Wp  = g_W + (size_t)by * 32 * 4096;

    // ldmatrix base offsets (bytes within a stage)
    const int aRow = mbase + ((lane >> 3) & 1) * 8 + (lane & 7);
    const uint32_t aOff = (uint32_t)(aRow * ROWB + ((lane >> 4) & 1) * 16);
    const int bRow = nbase + ((lane >> 4) & 1) * 8 + (lane & 7);
    const uint32_t bOff = (uint32_t)(bRow * ROWB + ((lane >> 3) & 1) * 16);

    float acc[2][4];
#pragma unroll
    for (int a = 0; a < 2; ++a)
#pragma unroll
        for (int b = 0; b < 4; ++b) acc[a][b] = 0.f;

    auto issue_stage = [&](int chunk, int st) {
        const int kbase = chunk * 64;
#pragma unroll
        for (int j = 0; j < 6; ++j) {
            if (j < 4) {                                  // A: 1024 x 16B
                const int id = tid + j * 256;
                const int row = id >> 4, c16 = id & 15;
                cp16(ab + A_OFF + st * A_STG + row * ROWB + c16 * 16,
                     X + (size_t)(mblock + row) * 4096 + kbase + c16 * 4);
            } else {                                      // B: 512 x 16B
                const int id2 = tid + (j - 4) * 256;
                const int row = id2 >> 4, c16 = id2 & 15;
                cp16(ab + B_OFF + st * B_STG + row * ROWB + c16 * 16,
                     Wp + (size_t)row * 4096 + kbase + c16 * 4);
            }
        }
    };

    // prologue: stages 0..2
#pragma unroll
    for (int p = 0; p < 3; ++p) {
        issue_stage(p, p);
        asm volatile("cp.async.commit_group;\n" ::: "memory");
    }

#pragma unroll 1
    for (int c = 0; c < 64; ++c) {
        const int st = c & 3;
        asm volatile("cp.async.wait_group 2;\n" ::: "memory");
        __syncthreads();

        if (c + 3 < 64) issue_stage(c + 3, (c + 3) & 3);
        asm volatile("cp.async.commit_group;\n" ::: "memory");

        const uint32_t aS = ab + A_OFF + st * A_STG + aOff;
        const uint32_t bS = ab + B_OFF + st * B_STG + bOff;

        uint32_t af[2][4], bf[2][4];
        ldsm_x4(af[0], aS);
        ldsm_x4(bf[0], bS);

#pragma unroll
        for (int kk = 0; kk < 8; ++kk) {
            const int cur = kk & 1, nxt = cur ^ 1;
            if (kk < 7) {
                const uint32_t kadd = (uint32_t)((kk + 1) * 32);
                ldsm_x4(af[nxt], aS + kadd);
                ldsm_x4(bf[nxt], bS + kadd);
            }
            const uint32_t a0 = f2tf32(af[cur][0]);
            const uint32_t a1 = f2tf32(af[cur][1]);
            const uint32_t a2 = f2tf32(af[cur][2]);
            const uint32_t a3 = f2tf32(af[cur][3]);
#pragma unroll
            for (int ns = 0; ns < 2; ++ns) {
                asm volatile(
                    "mma.sync.aligned.m16n8k8.row.col.f32.tf32.tf32.f32 "
                    "{%0,%1,%2,%3}, {%4,%5,%6,%7}, {%8,%9}, {%0,%1,%2,%3};\n"
                    : "+f"(acc[ns][0]), "+f"(acc[ns][1]),
                      "+f"(acc[ns][2]), "+f"(acc[ns][3])
                    : "r"(a0), "r"(a1), "r"(a2), "r"(a3),
                      "r"(bf[cur][ns * 2]), "r"(bf[cur][ns * 2 + 1]));
            }
        }
    }

    // ---- epilogue: bias + LeakyReLU, direct store ----
    const int grp = lane >> 2, qid = lane & 3;
#pragma unroll
    for (int ns = 0; ns < 2; ++ns) {
        const int col = by * 32 + nbase + ns * 8 + qid * 2;
        const float bb0 = __ldg(&bias[col]);
        const float bb1 = __ldg(&bias[col + 1]);
        const int r0 = mblock + mbase + grp;
        const int r1 = r0 + 8;

        float v00 = acc[ns][0] + bb0; v00 = (v00 >= 0.f) ? v00 : 0.001f * v00;
        float v01 = acc[ns][1] + bb1; v01 = (v01 >= 0.f) ? v01 : 0.001f * v01;
        float v10 = acc[ns][2] + bb0; v10 = (v10 >= 0.f) ? v10 : 0.001f * v10;
        float v11 = acc[ns][3] + bb1; v11 = (v11 >= 0.f) ? v11 : 0.001f * v11;

        *reinterpret_cast<float2*>(&out[(size_t)r0 * 64 + col]) = make_float2(v00, v01);
        *reinterpret_cast<float2*>(&out[(size_t)r1 * 64 + col]) = make_float2(v10, v11);
    }
}

// =====================================================================
// Launch
// =====================================================================
extern "C" void kernel_launch(void* const* d_in, const int* in_sizes, int n_in,
                              void* d_out, int out_size) {
    const float* x      = (const float*)d_in[0];   // [8192,1,64,8,8]
    const float* conv_w = (const float*)d_in[1];   // [64,84,8,8]
    const float* conv_b = (const float*)d_in[2];   // [64]
    float*       out    = (float*)d_out;           // [8192,64]

    cudaFuncSetAttribute(gemm_kernel,
                         cudaFuncAttributeMaxDynamicSharedMemorySize, SMEM_REQ);

    weff_kernel<<<dim3(64, 4), 256>>>(conv_w);
    gemm_kernel<<<dim3(128, 2), 256, SMEM_REQ>>>(x, conv_b, out);
}

// round 9
// speedup vs baseline: 1.6019x; 1.3993x over previous
#include <cuda_runtime.h>
#include <cstdint>

#define DEV_INLINE __device__ __forceinline__

// =====================================================================
// Compile-time DWT matrix: coeff[c] = sum_t M[c][t] * x[t]   (84 x 64)
// =====================================================================
struct MArr { float v[84 * 64]; };

constexpr int refl(int i, int n) {
    if (i < 0) i = -i;
    if (i >= n) i = 2 * (n - 1) - i;
    return i;
}

constexpr MArr build_M() {
    const float LO[8] = { -0.010597401784997278f, 0.032883011666982945f,
                           0.030841381835986965f, -0.18703481171888114f,
                          -0.02798376941698385f,  0.6308807679295904f,
                           0.7148465705525415f,   0.23037781330885523f };
    const float HI[8] = { -0.23037781330885523f,  0.7148465705525415f,
                          -0.6308807679295904f,  -0.02798376941698385f,
                           0.18703481171888114f,  0.030841381835986965f,
                           0.032883011666982945f, -0.010597401784997278f };
    MArr m{};
    for (int t = 0; t < 64; ++t) {
        float lo1[35] = {}, hi1[35] = {};
        float lo2[21] = {}, hi2[21] = {};
        for (int i = 0; i < 35; ++i) {
            float l = 0.f, h = 0.f;
            for (int j = 0; j < 8; ++j) {
                int idx = refl(2 * i + j - 6, 64);
                float xv = (idx == t) ? 1.0f : 0.0f;
                l += xv * LO[7 - j]; h += xv * HI[7 - j];
            }
            lo1[i] = l; hi1[i] = h;
        }
        for (int i = 0; i < 21; ++i) {
            float l = 0.f, h = 0.f;
            for (int j = 0; j < 8; ++j) {
                int idx = refl(2 * i + j - 6, 35);
                l += lo1[idx] * LO[7 - j]; h += lo1[idx] * HI[7 - j];
            }
            lo2[i] = l; hi2[i] = h;
        }
        for (int i = 0; i < 14; ++i) {
            float l = 0.f, h = 0.f;
            for (int j = 0; j < 8; ++j) {
                int idx = refl(2 * i + j - 6, 21);
                l += lo2[idx] * LO[7 - j]; h += lo2[idx] * HI[7 - j];
            }
            m.v[i * 64 + t]        = l;   // lo3
            m.v[(70 + i) * 64 + t] = h;   // hi3
        }
        for (int i = 0; i < 35; ++i) m.v[(14 + i) * 64 + t] = hi1[i];
        for (int i = 0; i < 21; ++i) m.v[(49 + i) * 64 + t] = hi2[i];
    }
    return m;
}

constexpr MArr M_TBL = build_M();
__device__ const MArr g_Mc = M_TBL;

__device__ float g_W[64 * 4096];            // Weff[k][t*64+hw], tf32-rounded
__device__ float g_P[4 * 8192 * 64];        // split-K partials

// =====================================================================
// Kernel A: Weff[k][t*64+hw] = sum_c M[c][t] * conv_w[k][c][hw]
// =====================================================================
__global__ void weff_kernel(const float* __restrict__ conv_w) {
    __shared__ float cw[84 * 64];
    __shared__ float Ms[84 * 16];
    const int k   = blockIdx.x;
    const int q   = blockIdx.y;
    const int tid = threadIdx.x;

    for (int i = tid; i < 84 * 64; i += 256) cw[i] = conv_w[k * 84 * 64 + i];
    for (int i = tid; i < 84 * 16; i += 256) {
        const int c = i >> 4, tt = i & 15;
        Ms[i] = g_Mc.v[c * 64 + q * 16 + tt];
    }
    __syncthreads();

    const int hw = tid & 63;
    const int tg = tid >> 6;
    float acc[4] = {0.f, 0.f, 0.f, 0.f};

#pragma unroll 6
    for (int c = 0; c < 84; ++c) {
        const float v = cw[c * 64 + hw];
        const float* m = &Ms[c * 16 + tg * 4];
#pragma unroll
        for (int i = 0; i < 4; ++i) acc[i] = fmaf(v, m[i], acc[i]);
    }
#pragma unroll
    for (int i = 0; i < 4; ++i) {
        const int t = q * 16 + tg * 4 + i;
        uint32_t r;
        asm("cvt.rna.tf32.f32 %0, %1;" : "=r"(r) : "f"(acc[i]));
        g_W[k * 4096 + t * 64 + hw] = __uint_as_float(r);
    }
}

// =====================================================================
// Kernel B: split-K tf32 GEMM partials.
// CTA: M=64, N=64, 4 warps (2m x 2n), warp tile m32 x n32.
// KC=32 per stage, 3-stage cp.async; grid (128 m-tiles, 4 k-splits).
// 55.3 KB smem -> up to 4 CTAs/SM; grid 512 = single wave ~3.5 CTAs/SM.
// =====================================================================
constexpr int KSPLIT  = 4;
constexpr int KRANGE  = 4096 / KSPLIT;       // 1024
constexpr int KC      = 32;
constexpr int NCHUNK  = KRANGE / KC;         // 32
constexpr int ROWB    = 144;                 // 32 f32 + 16B pad
constexpr int A_STG   = 64 * ROWB;           // 9216
constexpr int B_STG   = 64 * ROWB;           // 9216
constexpr int A_OFF   = 0;
constexpr int B_OFF   = 3 * A_STG;           // 27648
constexpr int SMEM_REQ = B_OFF + 3 * B_STG;  // 55296

DEV_INLINE void cp16(uint32_t daddr, const void* src) {
    asm volatile("cp.async.cg.shared.global [%0], [%1], 16;\n" :: "r"(daddr), "l"(src));
}
DEV_INLINE void ldsm_x4(uint32_t* r, uint32_t addr) {
    asm volatile("ldmatrix.sync.aligned.m8n8.x4.shared.b16 {%0,%1,%2,%3}, [%4];"
                 : "=r"(r[0]), "=r"(r[1]), "=r"(r[2]), "=r"(r[3]) : "r"(addr));
}
DEV_INLINE uint32_t f2tf32(uint32_t f) {
    uint32_t r; asm("cvt.rna.tf32.f32 %0, %1;" : "=r"(r) : "r"(f)); return r;
}

__global__ __launch_bounds__(128, 4)
void gemm_kernel(const float* __restrict__ X) {
    extern __shared__ char dsm[];
    uint32_t ab;
    asm("{ .reg .u64 t; cvta.to.shared.u64 t, %1; cvt.u32.u64 %0, t; }"
        : "=r"(ab) : "l"(dsm));

    const int tid    = threadIdx.x;           // 128
    const int lane   = tid & 31;
    const int wid    = tid >> 5;              // 0..3
    const int mbase  = (wid >> 1) * 32;       // warp m origin (0/32)
    const int nbase  = (wid & 1) * 32;        // warp n origin (0/32)
    const int mblock = blockIdx.x * 64;
    const int ky     = blockIdx.y;            // k-split index
    const int kgbase = ky * KRANGE;

    // ldmatrix lane offsets within a stage (bytes)
    const int aRow = mbase + ((lane >> 3) & 1) * 8 + (lane & 7);
    const uint32_t aOff = (uint32_t)(aRow * ROWB + ((lane >> 4) & 1) * 16);
    const int bRow = nbase + ((lane >> 4) & 1) * 8 + (lane & 7);
    const uint32_t bOff = (uint32_t)(bRow * ROWB + ((lane >> 3) & 1) * 16);

    float acc[2][4][4];
#pragma unroll
    for (int a = 0; a < 2; ++a)
#pragma unroll
        for (int b = 0; b < 4; ++b)
#pragma unroll
            for (int d = 0; d < 4; ++d) acc[a][b][d] = 0.f;

    // one KC=32 chunk into stage st: A 512 x 16B + B 512 x 16B
    auto issue_stage = [&](int chunk, int st) {
        const int kbase = kgbase + chunk * KC;
#pragma unroll
        for (int j = 0; j < 8; ++j) {
            const int id = (j < 4) ? (tid + j * 128) : (tid + (j - 4) * 128);
            const int row = id >> 3, c16 = id & 7;
            if (j < 4)
                cp16(ab + A_OFF + st * A_STG + row * ROWB + c16 * 16,
                     X + (size_t)(mblock + row) * 4096 + kbase + c16 * 4);
            else
                cp16(ab + B_OFF + st * B_STG + row * ROWB + c16 * 16,
                     g_W + (size_t)row * 4096 + kbase + c16 * 4);
        }
    };

    issue_stage(0, 0);
    asm volatile("cp.async.commit_group;\n" ::: "memory");
    issue_stage(1, 1);
    asm volatile("cp.async.commit_group;\n" ::: "memory");

#pragma unroll 1
    for (int c = 0; c < NCHUNK; ++c) {
        const int st = c % 3;
        asm volatile("cp.async.wait_group 1;\n" ::: "memory");
        __syncthreads();

        if (c + 2 < NCHUNK) issue_stage(c + 2, (c + 2) % 3);
        asm volatile("cp.async.commit_group;\n" ::: "memory");

        const uint32_t aS = ab + A_OFF + st * A_STG + aOff;
        const uint32_t bS = ab + B_OFF + st * B_STG + bOff;

        uint32_t af[2][8], bf[2][8];
        ldsm_x4(af[0] + 0, aS);
        ldsm_x4(af[0] + 4, aS + 16 * ROWB);
        ldsm_x4(bf[0] + 0, bS);
        ldsm_x4(bf[0] + 4, bS + 16 * ROWB);

#pragma unroll
        for (int kk = 0; kk < 4; ++kk) {
            const int cur = kk & 1, nxt = cur ^ 1;
            if (kk < 3) {
                const uint32_t kadd = (uint32_t)((kk + 1) * 32);
                ldsm_x4(af[nxt] + 0, aS + kadd);
                ldsm_x4(af[nxt] + 4, aS + kadd + 16 * ROWB);
                ldsm_x4(bf[nxt] + 0, bS + kadd);
                ldsm_x4(bf[nxt] + 4, bS + kadd + 16 * ROWB);
            }
            uint32_t a[8];
#pragma unroll
            for (int i = 0; i < 8; ++i) a[i] = f2tf32(af[cur][i]);
#pragma unroll
            for (int mi = 0; mi < 2; ++mi) {
#pragma unroll
                for (int ns = 0; ns < 4; ++ns) {
                    asm volatile(
                        "mma.sync.aligned.m16n8k8.row.col.f32.tf32.tf32.f32 "
                        "{%0,%1,%2,%3}, {%4,%5,%6,%7}, {%8,%9}, {%0,%1,%2,%3};\n"
                        : "+f"(acc[mi][ns][0]), "+f"(acc[mi][ns][1]),
                          "+f"(acc[mi][ns][2]), "+f"(acc[mi][ns][3])
                        : "r"(a[mi * 4 + 0]), "r"(a[mi * 4 + 1]),
                          "r"(a[mi * 4 + 2]), "r"(a[mi * 4 + 3]),
                          "r"(bf[cur][ns * 2]), "r"(bf[cur][ns * 2 + 1]));
                }
            }
        }
    }

    // ---- write partials ----
    float* pp = g_P + ((size_t)ky * 8192 + mblock) * 64;
    const int grp = lane >> 2, qid = lane & 3;
#pragma unroll
    for (int mi = 0; mi < 2; ++mi) {
#pragma unroll
        for (int ns = 0; ns < 4; ++ns) {
            const int col = nbase + ns * 8 + qid * 2;
            const int r0  = mbase + mi * 16 + grp;
            const int r1  = r0 + 8;
            *reinterpret_cast<float2*>(pp + (size_t)r0 * 64 + col) =
                make_float2(acc[mi][ns][0], acc[mi][ns][1]);
            *reinterpret_cast<float2*>(pp + (size_t)r1 * 64 + col) =
                make_float2(acc[mi][ns][2], acc[mi][ns][3]);
        }
    }
}

// =====================================================================
// Kernel C: reduce 4 partials + bias + LeakyReLU -> out
// =====================================================================
__global__ void reduce_kernel(const float* __restrict__ bias,
                              float* __restrict__ out) {
    const int idx  = blockIdx.x * 256 + threadIdx.x;   // float4 index
    const int base = idx * 4;
    const int col  = base & 63;

    const float4 p0 = *reinterpret_cast<const float4*>(g_P + base);
    const float4 p1 = *reinterpret_cast<const float4*>(g_P + 524288 + base);
    const float4 p2 = *reinterpret_cast<const float4*>(g_P + 2 * 524288 + base);
    const float4 p3 = *reinterpret_cast<const float4*>(g_P + 3 * 524288 + base);
    const float4 bb = *reinterpret_cast<const float4*>(bias + col);

    float v0 = p0.x + p1.x + p2.x + p3.x + bb.x;
    float v1 = p0.y + p1.y + p2.y + p3.y + bb.y;
    float v2 = p0.z + p1.z + p2.z + p3.z + bb.z;
    float v3 = p0.w + p1.w + p2.w + p3.w + bb.w;
    v0 = (v0 >= 0.f) ? v0 : 0.001f * v0;
    v1 = (v1 >= 0.f) ? v1 : 0.001f * v1;
    v2 = (v2 >= 0.f) ? v2 : 0.001f * v2;
    v3 = (v3 >= 0.f) ? v3 : 0.001f * v3;

    *reinterpret_cast<float4*>(out + base) = make_float4(v0, v1, v2, v3);
}

// =====================================================================
// Launch
// =====================================================================
extern "C" void kernel_launch(void* const* d_in, const int* in_sizes, int n_in,
                              void* d_out, int out_size) {
    const float* x      = (const float*)d_in[0];   // [8192,1,64,8,8]
    const float* conv_w = (const float*)d_in[1];   // [64,84,8,8]
    const float* conv_b = (const float*)d_in[2];   // [64]
    float*       out    = (float*)d_out;           // [8192,64]

    cudaFuncSetAttribute(gemm_kernel,
                         cudaFuncAttributeMaxDynamicSharedMemorySize, SMEM_REQ);

    weff_kernel<<<dim3(64, 4), 256>>>(conv_w);
    gemm_kernel<<<dim3(128, KSPLIT), 128, SMEM_REQ>>>(x);
    reduce_kernel<<<512, 256>>>(conv_b, out);
}